// round 14
// baseline (speedup 1.0000x reference)
#include <cuda_runtime.h>

// 2-layer LSTM (HID=10) + linear head, B=2048, T=1024, future=64.
// Round 14: gate-pair packed FFMA2 accumulators (no psum FADDs) with
// duplicated-h smem ((h[m],h[m]) via one ld.shared.b64), duplicated x
// staging, blin folded into head acc, uniform 86x256 grid (2 warps/SMSP
// everywhere, one wave). tanh.approx activations, i/f/o rows pre-halved.

#define HID 10
#define T_FIXED 1024

typedef unsigned long long u64;

__device__ __forceinline__ u64 pack2(float lo, float hi) {
    u64 d; asm("mov.b64 %0, {%1, %2};" : "=l"(d) : "f"(lo), "f"(hi)); return d;
}
__device__ __forceinline__ void unpack2(u64 d, float& lo, float& hi) {
    asm("mov.b64 {%0, %1}, %2;" : "=f"(lo), "=f"(hi) : "l"(d));
}
__device__ __forceinline__ u64 ffma2(u64 a, u64 b, u64 c) {
    u64 d; asm("fma.rn.f32x2 %0, %1, %2, %3;" : "=l"(d) : "l"(a), "l"(b), "l"(c));
    return d;
}
__device__ __forceinline__ float tanh_hw(float v) {
    float r; asm("tanh.approx.f32 %0, %1;" : "=f"(r) : "f"(v)); return r;
}

// Gates gi,gf,go arrive PRE-HALVED (weights/biases scaled by 0.5).
__device__ __forceinline__ float cell_update_h(
    float gi_h, float gf_h, float gg, float go_h, float& c)
{
    float si = fmaf(tanh_hw(gi_h), 0.5f, 0.5f);
    float sf = fmaf(tanh_hw(gf_h), 0.5f, 0.5f);
    float so = fmaf(tanh_hw(go_h), 0.5f, 0.5f);
    float tg = tanh_hw(gg);
    c = fmaf(sf, c, si * tg);
    return so * tanh_hw(c);
}

// 8-byte smem load (duplicated-h pair), ordered after same-warp stores.
__device__ __forceinline__ u64 lds64(const float* p) {
    u64 d; unsigned a = (unsigned)__cvta_generic_to_shared(p);
    asm volatile("ld.shared.b64 %0, [%1];" : "=l"(d) : "r"(a) : "memory");
    return d;
}

// Per-warp smem layout (floats):
//   H1D dup [3][24] | H2D dup [3][24] | X dup [3][34] | Y [3][20]
#define SW_H1D 0
#define SW_H2D 72
#define SW_X   144
#define SW_Y   246
#define SW_WARP 308       // 1232 B, 16B-aligned stride
#define WPB 8             // warps per block

__global__ void __launch_bounds__(32 * WPB, 1)
lstm2_seq_kernel(
    const float* __restrict__ x,
    const float* __restrict__ W_ih1, const float* __restrict__ W_hh1,
    const float* __restrict__ b_ih1, const float* __restrict__ b_hh1,
    const float* __restrict__ W_ih2, const float* __restrict__ W_hh2,
    const float* __restrict__ b_ih2, const float* __restrict__ b_hh2,
    const float* __restrict__ W_lin, const float* __restrict__ b_lin,
    float* __restrict__ out,
    int B, int T, int outT)
{
    __shared__ __align__(16) float sm[WPB * SW_WARP];

    const int lane   = threadIdx.x & 31;
    const int warpIn = threadIdx.x >> 5;
    const int warpGl = blockIdx.x * WPB + warpIn;
    const int g      = lane / 10;          // 0..2 active groups; 3 = idle
    const int k      = lane - g * 10;      // unit index within group
    const int gc     = (g < 3) ? g : 0;
    const int warpB0 = warpGl * 3;
    const int b      = warpB0 + gc;
    const bool alane = (g < 3) && (b < B);
    float* sw = sm + warpIn * SW_WARP;

    // ---- per-lane weights, gate-PAIR packed: pair0=(i,f), pair1=(g,o).
    //      i/f/o rows pre-scaled by 0.5 (g row unscaled). ----
    const int r0 = 0 * HID + k, r1 = 1 * HID + k;
    const int r2 = 2 * HID + k, r3 = 3 * HID + k;

    u64 whh1p[2][HID], wih2p[2][HID], whh2p[2][HID], wlin0[HID];
#pragma unroll
    for (int m = 0; m < HID; m++) {
        whh1p[0][m] = pack2(0.5f * W_hh1[r0*HID+m], 0.5f * W_hh1[r1*HID+m]);
        whh1p[1][m] = pack2(       W_hh1[r2*HID+m], 0.5f * W_hh1[r3*HID+m]);
        wih2p[0][m] = pack2(0.5f * W_ih2[r0*HID+m], 0.5f * W_ih2[r1*HID+m]);
        wih2p[1][m] = pack2(       W_ih2[r2*HID+m], 0.5f * W_ih2[r3*HID+m]);
        whh2p[0][m] = pack2(0.5f * W_hh2[r0*HID+m], 0.5f * W_hh2[r1*HID+m]);
        whh2p[1][m] = pack2(       W_hh2[r2*HID+m], 0.5f * W_hh2[r3*HID+m]);
        wlin0[m]    = pack2(W_lin[m], 0.0f);
    }
    const u64 wih1p0 = pack2(0.5f * W_ih1[r0], 0.5f * W_ih1[r1]);
    const u64 wih1p1 = pack2(       W_ih1[r2], 0.5f * W_ih1[r3]);
    const u64 b1p0 = pack2(0.5f * (b_ih1[r0] + b_hh1[r0]),
                           0.5f * (b_ih1[r1] + b_hh1[r1]));
    const u64 b1p1 = pack2(       (b_ih1[r2] + b_hh1[r2]),
                           0.5f * (b_ih1[r3] + b_hh1[r3]));
    const u64 b2p0 = pack2(0.5f * (b_ih2[r0] + b_hh2[r0]),
                           0.5f * (b_ih2[r1] + b_hh2[r1]));
    const u64 b2p1 = pack2(       (b_ih2[r2] + b_hh2[r2]),
                           0.5f * (b_ih2[r3] + b_hh2[r3]));
    const u64 blinp = pack2(b_lin[0], 0.0f);

    float c1 = 0.0f, c2 = 0.0f;

    // ---- x / y staging ----
    float xr0 = 0.0f, xr1 = 0.0f;
    auto ldg_chunk = [&](int t0, float& a0, float& a1) {
        int bs = lane >> 4, col = lane & 15;
        int bb0 = warpB0 + bs;
        a0 = (bb0 < B) ? x[(size_t)bb0 * T + t0 + col] : 0.0f;
        int bb1 = warpB0 + 2;
        a1 = (lane < 16 && bb1 < B) ? x[(size_t)bb1 * T + t0 + lane] : 0.0f;
    };
    auto sts_chunk = [&](float a0, float a1) {    // duplicated store
        int bs = lane >> 4, col = lane & 15;
        float* p = sw + SW_X + bs * 34 + 2 * col;
        p[0] = a0; p[1] = a0;
        if (lane < 16) {
            float* q = sw + SW_X + 2 * 34 + 2 * lane;
            q[0] = a1; q[1] = a1;
        }
    };
    auto flush_y = [&](int t0) {
#pragma unroll
        for (int r = 0; r < 2; r++) {
            int idx = lane + r * 32;
            if (idx < 48) {
                int bs = idx >> 4, col = idx & 15;
                int bb = warpB0 + bs;
                if (bb < B && t0 + col < outT)
                    out[(size_t)bb * outT + t0 + col] = sw[SW_Y + bs * 20 + col];
            }
        }
    };

    // prologue: commit chunk 0, prefetch chunk 16
    { float a0, a1; ldg_chunk(0, a0, a1); sts_chunk(a0, a1); }
    if (T > 16) ldg_chunk(16, xr0, xr1);

    // carried duplicated h2 vector (h2(-1) = 0)
    u64 vd[HID];
#pragma unroll
    for (int m = 0; m < HID; m++) vd[m] = pack2(0.0f, 0.0f);

    // gates for step 0 (h1(-1) = 0)
    u64 xx0 = lds64(sw + SW_X + gc * 34);
    u64 G0 = ffma2(wih1p0, xx0, b1p0);
    u64 G1 = ffma2(wih1p1, xx0, b1p1);

    // ---- pipelined main loop: steps 0 .. T-2 ----
#pragma unroll 1
    for (int t = 0; t < T - 1; t++) {
        // A = b2 + Whh2 . h2(t-1), head y(t-1) — from carried vd
        u64 A0 = b2p0, A1 = b2p1, Y = blinp;
#pragma unroll
        for (int m = 0; m < HID; m++) {
            A0 = ffma2(whh2p[0][m], vd[m], A0);
            A1 = ffma2(whh2p[1][m], vd[m], A1);
            Y  = ffma2(wlin0[m],    vd[m], Y);
        }
        {
            float yl, yh; unpack2(Y, yl, yh);
            if (alane && k == 0) sw[SW_Y + gc * 20 + ((t - 1) & 15)] = yl + yh;
        }

        // layer-1 activation for step t (consumes G — gates packed (i,f),(g,o))
        float gi, gf, gg, go;
        unpack2(G0, gi, gf); unpack2(G1, gg, go);
        float h1 = cell_update_h(gi, gf, gg, go, c1);
        if (alane) {
            float* p = sw + SW_H1D + gc * 24 + 2 * k;
            p[0] = h1; p[1] = h1;
        }

        // x(t+1)
        int tn = t + 1;
        if ((tn & 15) == 0) {
            sts_chunk(xr0, xr1);
            int t0n = tn + 16;
            if (t0n < T) ldg_chunk(t0n, xr0, xr1);
        }
        u64 xx = lds64(sw + SW_X + gc * 34 + 2 * (tn & 15));
        u64 N0 = ffma2(wih1p0, xx, b1p0);
        u64 N1 = ffma2(wih1p1, xx, b1p1);

        // shared h1(t) pass: feeds ih2 (step t) and hh1 (step t+1)
#pragma unroll
        for (int m = 0; m < HID; m++) {
            u64 wd = lds64(sw + SW_H1D + gc * 24 + 2 * m);
            A0 = ffma2(wih2p[0][m], wd, A0);
            A1 = ffma2(wih2p[1][m], wd, A1);
            N0 = ffma2(whh1p[0][m], wd, N0);
            N1 = ffma2(whh1p[1][m], wd, N1);
        }
        G0 = N0; G1 = N1;

        // layer-2 activation for step t; dup-store, re-carry vd
        float ai, af, ag, ao;
        unpack2(A0, ai, af); unpack2(A1, ag, ao);
        float h2 = cell_update_h(ai, af, ag, ao, c2);
        if (alane) {
            float* p = sw + SW_H2D + gc * 24 + 2 * k;
            p[0] = h2; p[1] = h2;
        }
#pragma unroll
        for (int m = 0; m < HID; m++)
            vd[m] = lds64(sw + SW_H2D + gc * 24 + 2 * m);

        if ((t & 15) == 0 && t > 0) flush_y(t - 16);
    }

    // ---- pending y(T-2) from vd = h2(T-2) ----
    {
        u64 Y = blinp;
#pragma unroll
        for (int m = 0; m < HID; m++) Y = ffma2(wlin0[m], vd[m], Y);
        float yl, yh; unpack2(Y, yl, yh);
        if (alane && k == 0) sw[SW_Y + gc * 20 + ((T - 2) & 15)] = yl + yh;
    }

    // ---- tail: step T-1 with x[T-1], then future steps with y feedback ----
    u64 xx = lds64(sw + SW_X + gc * 34 + 2 * 15);   // (x[T-1], x[T-1])
#pragma unroll 1
    for (int t = T - 1; t < outT; t++) {
        // layer 1
        u64 N0 = ffma2(wih1p0, xx, b1p0);
        u64 N1 = ffma2(wih1p1, xx, b1p1);
#pragma unroll
        for (int m = 0; m < HID; m++) {
            u64 wd = lds64(sw + SW_H1D + gc * 24 + 2 * m);   // h1(t-1)
            N0 = ffma2(whh1p[0][m], wd, N0);
            N1 = ffma2(whh1p[1][m], wd, N1);
        }
        float gi, gf, gg, go;
        unpack2(N0, gi, gf); unpack2(N1, gg, go);
        float h1 = cell_update_h(gi, gf, gg, go, c1);
        if (alane) {
            float* p = sw + SW_H1D + gc * 24 + 2 * k;
            p[0] = h1; p[1] = h1;
        }

        // layer 2 (vd holds h2(t-1))
        u64 A0 = b2p0, A1 = b2p1;
#pragma unroll
        for (int m = 0; m < HID; m++) {
            u64 wd = lds64(sw + SW_H1D + gc * 24 + 2 * m);   // h1(t)
            A0 = ffma2(wih2p[0][m], wd, A0);
            A1 = ffma2(wih2p[1][m], wd, A1);
            A0 = ffma2(whh2p[0][m], vd[m], A0);
            A1 = ffma2(whh2p[1][m], vd[m], A1);
        }
        float ai, af, ag, ao;
        unpack2(A0, ai, af); unpack2(A1, ag, ao);
        float h2 = cell_update_h(ai, af, ag, ao, c2);
        if (alane) {
            float* p = sw + SW_H2D + gc * 24 + 2 * k;
            p[0] = h2; p[1] = h2;
        }
#pragma unroll
        for (int m = 0; m < HID; m++)
            vd[m] = lds64(sw + SW_H2D + gc * 24 + 2 * m);

        // head from fresh h2(t)
        u64 Y = blinp;
#pragma unroll
        for (int m = 0; m < HID; m++) Y = ffma2(wlin0[m], vd[m], Y);
        float yl, yh; unpack2(Y, yl, yh);
        float y = yl + yh;
        if (alane && k == 0) sw[SW_Y + gc * 20 + (t & 15)] = y;
        xx = pack2(y, y);

        if ((t & 15) == 15) flush_y(t & ~15);
    }
    if (outT & 15) flush_y(outT & ~15);
}

extern "C" void kernel_launch(void* const* d_in, const int* in_sizes, int n_in,
                              void* d_out, int out_size)
{
    const float* x     = (const float*)d_in[0];
    const float* W_ih1 = (const float*)d_in[1];
    const float* W_hh1 = (const float*)d_in[2];
    const float* b_ih1 = (const float*)d_in[3];
    const float* b_hh1 = (const float*)d_in[4];
    const float* W_ih2 = (const float*)d_in[5];
    const float* W_hh2 = (const float*)d_in[6];
    const float* b_ih2 = (const float*)d_in[7];
    const float* b_hh2 = (const float*)d_in[8];
    const float* W_lin = (const float*)d_in[9];
    const float* b_lin = (const float*)d_in[10];
    float* out = (float*)d_out;

    const int T = T_FIXED;
    const int B = in_sizes[0] / T;          // 2048
    const int outT = out_size / B;          // T + future = 1088

    // 3 batches/warp, 8 warps/block -> 24 batches/block.
    // ceil(683/8) = 86 blocks <= 148 SMs: single wave, uniform 2 warps/SMSP.
    const int nWarps  = (B + 2) / 3;                    // 683
    const int nBlocks = (nWarps + WPB - 1) / WPB;       // 86
    lstm2_seq_kernel<<<nBlocks, 32 * WPB>>>(
        x, W_ih1, W_hh1, b_ih1, b_hh1,
        W_ih2, W_hh2, b_ih2, b_hh2,
        W_lin, b_lin, out, B, T, outT);
}